// round 1
// baseline (speedup 1.0000x reference)
#include <cuda_runtime.h>
#include <cstdint>

#define Bb 32
#define Qn 300
#define Mn 50
#define NCLS 92
#define BQ (Bb*Qn)      // 9600
#define BM (Bb*Mn)      // 1600
#define ROWS_PER_BLK 8

// device scratch (no allocations allowed)
__device__ float g_probs[BQ*NCLS];        // softmax probabilities, 3.5 MB
__device__ float g_idx_scratch[2*BM];     // fallback if out buffer holds only C

// ---------------------------------------------------------------------------
// Kernel 1: row softmax over 92 classes, one warp per row
// ---------------------------------------------------------------------------
__global__ void softmax_kernel(const float* __restrict__ logits) {
    int w    = (blockIdx.x * blockDim.x + threadIdx.x) >> 5;
    int lane = threadIdx.x & 31;
    if (w >= BQ) return;
    const float* xr = logits + (size_t)w * NCLS;
    float x0 = xr[lane];
    float x1 = xr[lane + 32];
    float x2 = (lane < NCLS - 64) ? xr[lane + 64] : -1e30f;
    float mx = fmaxf(x0, fmaxf(x1, x2));
    #pragma unroll
    for (int o = 16; o > 0; o >>= 1) mx = fmaxf(mx, __shfl_xor_sync(0xffffffffu, mx, o));
    float e0 = __expf(x0 - mx);
    float e1 = __expf(x1 - mx);
    float e2 = (lane < NCLS - 64) ? __expf(x2 - mx) : 0.f;
    float s = e0 + e1 + e2;
    #pragma unroll
    for (int o = 16; o > 0; o >>= 1) s += __shfl_xor_sync(0xffffffffu, s, o);
    float inv = __fdividef(1.f, s);
    float* pr = g_probs + (size_t)w * NCLS;
    pr[lane]      = e0 * inv;
    pr[lane + 32] = e1 * inv;
    if (lane < NCLS - 64) pr[lane + 64] = e2 * inv;
}

// ---------------------------------------------------------------------------
// Kernel 2: full cross cost matrix C[row, col], row in [0,9600), col in [0,1600)
// block = 8 pred rows x all 1600 target cols (targets staged in smem once)
// ---------------------------------------------------------------------------
__global__ void cost_kernel(const float4* __restrict__ pboxes,
                            const int*    __restrict__ tlab,
                            const float4* __restrict__ tboxes,
                            float*        __restrict__ Cout) {
    __shared__ float4 s_txy[BM];   // target xyxy
    __shared__ float  s_ta[BM];    // target area (from xyxy, matching reference)
    __shared__ int    s_tl[BM];    // target labels
    __shared__ float  s_prow[NCLS];

    int tid = threadIdx.x;
    for (int c = tid; c < BM; c += blockDim.x) {
        float4 tb = tboxes[c];
        float x1 = tb.x - 0.5f * tb.z, y1 = tb.y - 0.5f * tb.w;
        float x2 = tb.x + 0.5f * tb.z, y2 = tb.y + 0.5f * tb.w;
        s_txy[c] = make_float4(x1, y1, x2, y2);
        s_ta[c]  = (x2 - x1) * (y2 - y1);
        s_tl[c]  = tlab[c];
    }
    __syncthreads();

    for (int rr = 0; rr < ROWS_PER_BLK; rr++) {
        int row = blockIdx.x * ROWS_PER_BLK + rr;
        if (tid < NCLS) s_prow[tid] = g_probs[(size_t)row * NCLS + tid];
        __syncthreads();

        float4 pbv = pboxes[row];
        float px1 = pbv.x - 0.5f * pbv.z, py1 = pbv.y - 0.5f * pbv.w;
        float px2 = pbv.x + 0.5f * pbv.z, py2 = pbv.y + 0.5f * pbv.w;
        float pa  = (px2 - px1) * (py2 - py1);
        float* Crow = Cout + (size_t)row * BM;

        for (int c = tid; c < BM; c += blockDim.x) {
            float4 tb = tboxes[c];  // L1-resident after first row
            float cb = fabsf(pbv.x - tb.x) + fabsf(pbv.y - tb.y)
                     + fabsf(pbv.z - tb.z) + fabsf(pbv.w - tb.w);
            float4 t = s_txy[c];
            float iw = fmaxf(fminf(px2, t.z) - fmaxf(px1, t.x), 0.f);
            float ih = fmaxf(fminf(py2, t.w) - fmaxf(py1, t.y), 0.f);
            float inter = iw * ih;
            float uni = pa + s_ta[c] - inter;
            float ew = fmaxf(fmaxf(px2, t.z) - fminf(px1, t.x), 0.f);
            float eh = fmaxf(fmaxf(py2, t.w) - fminf(py1, t.y), 0.f);
            float ae = ew * eh;
            float giou = __fdividef(inter, uni) - __fdividef(ae - uni, ae);
            float cc = -s_prow[s_tl[c]];
            Crow[c] = fmaf(5.f, cb, cc) - 2.f * giou;
        }
        __syncthreads();
    }
}

// ---------------------------------------------------------------------------
// Kernel 3: per-batch Hungarian (JV shortest augmenting path), 1 block/batch.
// cost(t, q) = C[b, q, b*Mn + t]; n = Mn = 50 rows, m = Qn = 300 cols.
// 320 threads: tid < 300 own column tid; tid == 300 owns the virtual slot m.
// Mirrors the reference algorithm exactly (incl. lowest-index argmin ties).
// ---------------------------------------------------------------------------
__global__ void hungarian_kernel(const float* __restrict__ Cmat,
                                 float* __restrict__ outPred,
                                 float* __restrict__ outGt) {
    extern __shared__ float cost_s[];          // Mn*Qn floats (60000 B)
    __shared__ float u_s[Mn + 1];
    __shared__ int   p_s[Qn + 1];
    __shared__ int   way_s[Qn];
    __shared__ unsigned long long red_s[10];
    __shared__ unsigned long long res_s;
    __shared__ int   q_s[Mn];                  // col_of_row

    int b   = blockIdx.x;
    int tid = threadIdx.x;                     // 0..319

    // stage diagonal cost block (coalesced over t)
    for (int idx = tid; idx < Mn * Qn; idx += blockDim.x) {
        int qq = idx / Mn, t = idx % Mn;
        cost_s[t * Qn + qq] = Cmat[(size_t)(b * Qn + qq) * BM + b * Mn + t];
    }
    if (tid <= Mn) u_s[tid] = 0.f;
    for (int j = tid; j <= Qn; j += blockDim.x) p_s[j] = -1;
    __syncthreads();

    float v = 0.f;                             // column potential of my column
    for (int i = 0; i < Mn; i++) {
        float minv = 1e30f;
        bool  used = false;
        if (tid == Qn) p_s[Qn] = i;
        __syncthreads();
        int j0 = Qn;
        while (true) {
            if (tid == j0) used = true;
            int   i0  = p_s[j0];
            float ui0 = u_s[i0];
            unsigned long long key = ~0ull;
            if (tid < Qn && !used) {
                float cur = cost_s[i0 * Qn + tid] - ui0 - v;
                if (cur < minv) { minv = cur; way_s[tid] = j0; }
                unsigned int fu = __float_as_uint(minv);
                fu = (fu & 0x80000000u) ? ~fu : (fu | 0x80000000u);
                key = ((unsigned long long)fu << 32) | (unsigned int)tid;
            }
            #pragma unroll
            for (int o = 16; o > 0; o >>= 1)
                key = min(key, __shfl_xor_sync(0xffffffffu, key, o));
            if ((tid & 31) == 0) red_s[tid >> 5] = key;
            __syncthreads();
            if (tid < 32) {
                unsigned long long k2 = (tid < 10) ? red_s[tid] : ~0ull;
                #pragma unroll
                for (int o = 8; o > 0; o >>= 1)
                    k2 = min(k2, __shfl_xor_sync(0xffffffffu, k2, o));
                if (tid == 0) res_s = k2;
            }
            __syncthreads();
            unsigned long long r = res_s;
            int j1 = (int)(r & 0xffffffffu);
            unsigned int fu = (unsigned int)(r >> 32);
            fu = (fu & 0x80000000u) ? (fu & 0x7fffffffu) : ~fu;
            float delta = __uint_as_float(fu);
            if (used) { v -= delta; u_s[p_s[tid]] += delta; }
            else if (tid < Qn) { minv -= delta; }
            __syncthreads();
            j0 = j1;
            if (p_s[j0] == -1) break;
        }
        // augment along 'way' chain (serial, thread 0)
        if (tid == 0) {
            int j = j0;
            while (j != Qn) { int jn = way_s[j]; p_s[j] = p_s[jn]; j = jn; }
        }
        __syncthreads();
    }

    // col_of_row, then rank-sort (50 distinct ints) and emit
    if (tid < Qn) { int r = p_s[tid]; if (r >= 0) q_s[r] = tid; }
    __syncthreads();
    if (tid < Mn) {
        int myq = q_s[tid];
        int rank = 0;
        #pragma unroll 1
        for (int t2 = 0; t2 < Mn; t2++) rank += (q_s[t2] < myq) ? 1 : 0;
        outPred[b * Mn + rank] = (float)myq;
        outGt[b * Mn + rank]   = (float)tid;
    }
}

// ---------------------------------------------------------------------------
extern "C" void kernel_launch(void* const* d_in, const int* in_sizes, int n_in,
                              void* d_out, int out_size) {
    const float*  logits = (const float*)d_in[0];
    const float4* pboxes = (const float4*)d_in[1];
    const int*    tlab   = (const int*)d_in[2];
    const float4* tboxes = (const float4*)d_in[3];
    float* out = (float*)d_out;

    float *outPred, *outGt, *Cbase;
    if (out_size >= 2 * BM + BQ * BM) {
        outPred = out;
        outGt   = out + BM;
        Cbase   = out + 2 * BM;
    } else {
        void* sp = nullptr;
        cudaGetSymbolAddress(&sp, g_idx_scratch);
        outPred = (float*)sp;
        outGt   = outPred + BM;
        Cbase   = out;
    }

    softmax_kernel<<<(BQ * 32) / 256, 256>>>(logits);
    cost_kernel<<<BQ / ROWS_PER_BLK, 256>>>(pboxes, tlab, tboxes, Cbase);
    cudaFuncSetAttribute(hungarian_kernel,
                         cudaFuncAttributeMaxDynamicSharedMemorySize,
                         Mn * Qn * sizeof(float));
    hungarian_kernel<<<Bb, 320, Mn * Qn * sizeof(float)>>>(Cbase, outPred, outGt);
}